// round 4
// baseline (speedup 1.0000x reference)
#include <cuda_runtime.h>
#include <cuda_fp16.h>
#include <cstdint>

#define NN 200000
#define CH 128
#define KK 27
#define DD 3
#define CC (CH*CH)                  // 16384
#define WBLK (DD*KK)                // 81
#define SB 1024
#define TILE_M 128
#define NTIL ((NN + TILE_M - 1)/TILE_M)   // 1563

// smem layout (dynamic): sidx[27*128] ints, then 3 stages of (A 34816B + W 34816B)
#define SIDX_BYTES (KK*128*4)             // 13824
#define STAGE_BYTES (2*128*272)           // 69632
#define SMEM_TOTAL (SIDX_BYTES + 3*STAGE_BYTES)   // 222720

// ---------------- device scratch ----------------
__device__ __align__(16) __half g_xq[(size_t)(NN+1)*CH];
__device__ __align__(16) __half g_hq[(size_t)(NN+1)*CH];
__device__ __align__(16) __half g_wq[(size_t)2*WBLK*CC];
__device__ __align__(16) __half g_lwq[CC];
__device__ __align__(16) float g_hbuf[(size_t)NN*CH];
__device__ __align__(16) float g_ybuf[(size_t)NN*CH];
__device__ float g_ps[1600*CH], g_pq[1600*CH];
__device__ float g_sum[CH], g_sq[CH], g_r[CH];

// ---------------- helpers ----------------
__device__ __forceinline__ uint32_t smem_u32(const void* p) {
    uint32_t a;
    asm("{ .reg .u64 t; cvta.to.shared.u64 t, %1; cvt.u32.u64 %0, t; }" : "=r"(a) : "l"(p));
    return a;
}
__device__ __forceinline__ void cp16(uint32_t dst, const void* src) {
    asm volatile("cp.async.cg.shared.global [%0], [%1], 16;" :: "r"(dst), "l"(src));
}
__device__ __forceinline__ void cp_commit() { asm volatile("cp.async.commit_group;"); }
__device__ __forceinline__ void cp_wait2()  { asm volatile("cp.async.wait_group 2;"); }

__device__ __forceinline__ void mma16816h(float* d, const uint32_t* a, const uint32_t* b) {
    asm volatile(
        "mma.sync.aligned.m16n8k16.row.col.f32.f16.f16.f32 "
        "{%0,%1,%2,%3},{%4,%5,%6,%7},{%8,%9},{%0,%1,%2,%3};"
        : "+f"(d[0]), "+f"(d[1]), "+f"(d[2]), "+f"(d[3])
        : "r"(a[0]), "r"(a[1]), "r"(a[2]), "r"(a[3]), "r"(b[0]), "r"(b[1]));
}

// ---------------- prep kernels ----------------
__global__ void prep_w_kernel(const float* __restrict__ w1, const float* __restrict__ w2) {
    size_t i = (size_t)blockIdx.x*256 + threadIdx.x;
    if (i >= (size_t)2*WBLK*CC) return;
    size_t blk = i >> 14;
    int j = (int)(i & (CC-1));
    int ci = j >> 7, co = j & 127;
    float v = (blk < WBLK) ? w1[blk*CC + j] : w2[(blk - (size_t)WBLK)*CC + j];
    g_wq[blk*CC + (size_t)co*CH + ci] = __float2half_rn(v);
}

__global__ void prep_lin_kernel(const float* __restrict__ wlin) {
    int i = blockIdx.x*256 + threadIdx.x;
    if (i >= CC) return;
    int ci = i >> 7, co = i & 127;
    g_lwq[(size_t)co*CH + ci] = __float2half_rn(wlin[(size_t)ci*CH + co]);
}

__global__ void prep_x_kernel(const float* __restrict__ x) {
    size_t i = (size_t)blockIdx.x*256 + threadIdx.x;
    if (i >= (size_t)(NN+1)*CH) return;
    g_xq[i] = __float2half_rn(i < (size_t)NN*CH ? x[i] : 0.f);
}

// ---------------- fp16 sparse conv, cp.async 3-stage pipeline ----------------
__global__ void __launch_bounds__(256, 1)
conv_f16_kernel(const __half* __restrict__ Aq, const __half* __restrict__ Wq,
                const int* __restrict__ nbr, int ntaps, const float* __restrict__ bias,
                float* __restrict__ outp, float* __restrict__ ps, float* __restrict__ pq)
{
    extern __shared__ char smem[];
    int* sidx = (int*)smem;
    const uint32_t sb32 = smem_u32(smem);

    __shared__ float sm_s[2][128], sm_q[2][128];

    const int tid = threadIdx.x, lane = tid & 31, warp = tid >> 5;
    const int wm = warp >> 2, wn = warp & 3;
    const int gr = lane >> 2;
    const int gc = (lane & 3) * 2;
    const int row0 = blockIdx.x * TILE_M;

    // prefetch neighbor indices for all taps
    for (int i = tid; i < ntaps*128; i += 256) {
        int rr = i & 127, k = i >> 7;
        int r = row0 + rr;
        sidx[i] = (r < NN) ? (nbr ? nbr[(size_t)k*NN + r] : r) : NN;
    }
    __syncthreads();

    // issue lambda (macro-style)
    #define ISSUE_TAP(k)  do {                                                   \
        int _s = (k) % 3;                                                        \
        uint32_t _ab = sb32 + SIDX_BYTES + _s*STAGE_BYTES;                       \
        uint32_t _wb = _ab + 34816;                                              \
        const int* _sx = sidx + (k)*128;                                         \
        const __half* _wk = Wq + (size_t)(k)*CC;                                 \
        _Pragma("unroll")                                                        \
        for (int _p = 0; _p < 8; ++_p) {                                         \
            int _c = tid + _p*256;                                               \
            int _r = _c >> 4, _g = _c & 15;                                      \
            cp16(_ab + _r*272 + _g*16, Aq + (size_t)_sx[_r]*CH + _g*8);          \
            cp16(_wb + _r*272 + _g*16, _wk + (size_t)_r*CH + _g*8);              \
        }                                                                        \
    } while (0)

    // prologue: 3 committed groups (possibly empty)
    for (int k = 0; k < 3; ++k) {
        if (k < ntaps) ISSUE_TAP(k);
        cp_commit();
    }

    float acc[4][4][4];
    #pragma unroll
    for (int a = 0; a < 4; a++)
        #pragma unroll
        for (int b = 0; b < 4; b++)
            #pragma unroll
            for (int c = 0; c < 4; c++) acc[a][b][c] = 0.f;

    #pragma unroll 1
    for (int k = 0; k < ntaps; ++k) {
        cp_wait2();
        __syncthreads();
        const int s = k % 3;
        const __half* Ash = (const __half*)(smem + SIDX_BYTES + s*STAGE_BYTES);
        const __half* Wsh = Ash + 17408;

        #pragma unroll
        for (int kc = 0; kc < 8; ++kc) {
            const int kb = kc*16;
            uint32_t a_[4][4], b_[4][2];
            #pragma unroll
            for (int mi = 0; mi < 4; ++mi) {
                int rb = wm*64 + mi*16 + gr;
                int o0 = rb*136 + kb + gc;
                int o1 = (rb+8)*136 + kb + gc;
                a_[mi][0] = *(const uint32_t*)&Ash[o0];
                a_[mi][1] = *(const uint32_t*)&Ash[o1];
                a_[mi][2] = *(const uint32_t*)&Ash[o0 + 8];
                a_[mi][3] = *(const uint32_t*)&Ash[o1 + 8];
            }
            #pragma unroll
            for (int ni = 0; ni < 4; ++ni) {
                int nr = wn*32 + ni*8 + gr;
                int o = nr*136 + kb + gc;
                b_[ni][0] = *(const uint32_t*)&Wsh[o];
                b_[ni][1] = *(const uint32_t*)&Wsh[o + 8];
            }
            #pragma unroll
            for (int mi = 0; mi < 4; ++mi)
                #pragma unroll
                for (int ni = 0; ni < 4; ++ni)
                    mma16816h(acc[mi][ni], a_[mi], b_[ni]);
        }
        __syncthreads();   // all warps done reading stage s before overwrite
        if (k + 3 < ntaps) ISSUE_TAP(k + 3);
        cp_commit();
    }

    // ---------------- epilogue: store + optional fused stats ----------------
    #pragma unroll
    for (int mi = 0; mi < 4; ++mi) {
        int r_ = row0 + wm*64 + mi*16 + gr;
        #pragma unroll
        for (int ni = 0; ni < 4; ++ni) {
            int col = wn*32 + ni*8 + gc;
            float v0 = acc[mi][ni][0], v1 = acc[mi][ni][1];
            float v2 = acc[mi][ni][2], v3 = acc[mi][ni][3];
            if (bias) { v0 += bias[col]; v1 += bias[col+1]; v2 += bias[col]; v3 += bias[col+1]; }
            if (r_ < NN)     *(float2*)&outp[(size_t)r_*CH + col]     = make_float2(v0, v1);
            if (r_ + 8 < NN) *(float2*)&outp[(size_t)(r_+8)*CH + col] = make_float2(v2, v3);
        }
    }

    if (ps) {
        #pragma unroll
        for (int ni = 0; ni < 4; ++ni) {
            #pragma unroll
            for (int u = 0; u < 2; ++u) {
                float s = 0.f, q = 0.f;
                #pragma unroll
                for (int mi = 0; mi < 4; ++mi) {
                    float p0 = acc[mi][ni][u], p1 = acc[mi][ni][u+2];
                    s += p0 + p1; q += p0*p0 + p1*p1;
                }
                #pragma unroll
                for (int off = 4; off < 32; off <<= 1) {
                    s += __shfl_xor_sync(0xFFFFFFFF, s, off);
                    q += __shfl_xor_sync(0xFFFFFFFF, q, off);
                }
                if (gr == 0) {
                    int col = wn*32 + ni*8 + gc + u;
                    sm_s[wm][col] = s; sm_q[wm][col] = q;
                }
            }
        }
        __syncthreads();
        if (tid < 128) {
            ps[(size_t)blockIdx.x*CH + tid] = sm_s[0][tid] + sm_s[1][tid];
            pq[(size_t)blockIdx.x*CH + tid] = sm_q[0][tid] + sm_q[1][tid];
        }
    }
    #undef ISSUE_TAP
}

// ---------------- reduce partials -> g_sum, g_sq ----------------
__global__ void reduce_kernel(int cnt) {
    int c = threadIdx.x;
    float s = 0.f, q = 0.f;
    for (int b = 0; b < cnt; ++b) {
        s += g_ps[(size_t)b*CH + c];
        q += g_pq[(size_t)b*CH + c];
    }
    g_sum[c] = s; g_sq[c] = q;
}

// ---------------- BN + ReLU -> fp16 ----------------
__global__ void bn_relu_half_kernel(const float* __restrict__ h,
                                    const float* __restrict__ g, const float* __restrict__ b) {
    size_t i = (size_t)blockIdx.x*256 + threadIdx.x;
    if (i >= (size_t)(NN+1)*CH) return;
    int c = (int)(i & (CH-1));
    float val = 0.f;
    if (i < (size_t)NN*CH) {
        float m = g_sum[c] * (1.f/NN);
        float v = g_sq[c] * (1.f/NN) - m*m;
        float sc = g[c] * rsqrtf(v + 1e-5f);
        val = fmaxf((h[i] - m)*sc + b[c], 0.f);
    }
    g_hq[i] = __float2half_rn(val);
}

// ---------------- BN + accumulate into y ----------------
__global__ void bn_acc_kernel(const float* __restrict__ h,
                              const float* __restrict__ g, const float* __restrict__ b,
                              int first) {
    size_t i = (size_t)blockIdx.x*256 + threadIdx.x;
    if (i >= (size_t)NN*CH) return;
    int c = (int)(i & (CH-1));
    float m = g_sum[c] * (1.f/NN);
    float v = g_sq[c] * (1.f/NN) - m*m;
    float sc = g[c] * rsqrtf(v + 1e-5f);
    float bnv = (h[i] - m)*sc + b[c];
    g_ybuf[i] = first ? bnv : (g_ybuf[i] + bnv);
}

// ---------------- xout = relu(y + x) -> fp16 + column partial sums ----------------
__global__ void relu_add_kernel(const float* __restrict__ x) {
    int c = threadIdx.x;
    float s = 0.f;
    for (int r = blockIdx.x; r < NN; r += SB) {
        size_t i = (size_t)r*CH + c;
        float v = fmaxf(g_ybuf[i] + x[i], 0.f);
        g_hq[i] = __float2half_rn(v);
        s += v;
    }
    g_ps[(size_t)blockIdx.x*CH + c] = s;
    g_pq[(size_t)blockIdx.x*CH + c] = 0.f;
}

// ---------------- r = mean(xout) @ Wb + blin ----------------
__global__ void make_r_kernel(const float* __restrict__ wlin, const float* __restrict__ blin) {
    int co = threadIdx.x;
    float acc = blin[co];
    for (int ci = 0; ci < CH; ++ci)
        acc += (g_sum[ci] * (1.f/NN)) * wlin[(size_t)(CH + ci)*CH + co];
    g_r[co] = acc;
}

// ---------------- launch ----------------
extern "C" void kernel_launch(void* const* d_in, const int* in_sizes, int n_in,
                              void* d_out, int out_size) {
    const float* x    = (const float*)d_in[0];
    const float* w1   = (const float*)d_in[1];
    const float* w2   = (const float*)d_in[2];
    const float* g1   = (const float*)d_in[3];
    const float* b1   = (const float*)d_in[4];
    const float* g2   = (const float*)d_in[5];
    const float* b2   = (const float*)d_in[6];
    const float* wlin = (const float*)d_in[7];
    const float* blin = (const float*)d_in[8];
    const int*   nbr  = (const int*)d_in[9];
    float* outp = (float*)d_out;

    cudaFuncSetAttribute(conv_f16_kernel, cudaFuncAttributeMaxDynamicSharedMemorySize, SMEM_TOTAL);

    __half *xq, *hq, *wq, *lwq;
    float *h, *rptr;
    cudaGetSymbolAddress((void**)&xq,  g_xq);
    cudaGetSymbolAddress((void**)&hq,  g_hq);
    cudaGetSymbolAddress((void**)&wq,  g_wq);
    cudaGetSymbolAddress((void**)&lwq, g_lwq);
    cudaGetSymbolAddress((void**)&h,   g_hbuf);
    cudaGetSymbolAddress((void**)&rptr, g_r);
    float *ps, *pq;
    cudaGetSymbolAddress((void**)&ps, g_ps);
    cudaGetSymbolAddress((void**)&pq, g_pq);

    size_t nq = (size_t)(NN+1)*CH;
    int qgrid = (int)((nq + 255)/256);

    prep_w_kernel<<<(int)((2ull*WBLK*CC + 255)/256), 256>>>(w1, w2);
    prep_lin_kernel<<<(CC + 255)/256, 256>>>(wlin);
    prep_x_kernel<<<qgrid, 256>>>(x);

    for (int d = 0; d < DD; ++d) {
        const int* nb = nbr + (size_t)d*KK*NN;
        conv_f16_kernel<<<NTIL, 256, SMEM_TOTAL>>>(xq,
            wq + (size_t)d*KK*CC, nb, KK, nullptr, h, ps, pq);
        reduce_kernel<<<1, CH>>>(NTIL);
        bn_relu_half_kernel<<<qgrid, 256>>>(h, g1 + d*CH, b1 + d*CH);
        conv_f16_kernel<<<NTIL, 256, SMEM_TOTAL>>>(hq,
            wq + (size_t)(WBLK + d*KK)*CC, nb, KK, nullptr, h, ps, pq);
        reduce_kernel<<<1, CH>>>(NTIL);
        bn_acc_kernel<<<(int)(((size_t)NN*CH + 255)/256), 256>>>(h, g2 + d*CH, b2 + d*CH, d == 0);
    }

    relu_add_kernel<<<SB, CH>>>(x);
    reduce_kernel<<<1, CH>>>(SB);
    make_r_kernel<<<1, CH>>>(wlin, blin);
    conv_f16_kernel<<<NTIL, 256, SMEM_TOTAL>>>(hq, lwq, nullptr, 1, rptr, outp, nullptr, nullptr);
}

// round 5
// speedup vs baseline: 6.2175x; 6.2175x over previous
#include <cuda_runtime.h>
#include <cuda_fp16.h>
#include <cstdint>

#define NN 200000
#define CH 128
#define KK 27
#define DD 3
#define CC (CH*CH)                  // 16384
#define WBLK (DD*KK)                // 81
#define SB 1024
#define TILE_M 128
#define NTIL ((NN + TILE_M - 1)/TILE_M)   // 1563

// dynamic smem: sidx[27*128] ints, then 2 stages of (A 34816B + W 34816B)
#define SIDX_BYTES (KK*128*4)             // 13824
#define STAGE_BYTES (2*128*272)           // 69632
#define SMEM_TOTAL (SIDX_BYTES + 2*STAGE_BYTES)   // 153088

// ---------------- device scratch ----------------
__device__ __align__(16) __half g_xq[(size_t)(NN+1)*CH];
__device__ __align__(16) __half g_hq[(size_t)(NN+1)*CH];
__device__ __align__(16) __half g_wq[(size_t)2*WBLK*CC];
__device__ __align__(16) __half g_lwq[CC];
__device__ __align__(16) float g_hbuf[(size_t)NN*CH];
__device__ __align__(16) float g_ybuf[(size_t)NN*CH];
__device__ float g_ps[1600*CH], g_pq[1600*CH];
__device__ float g_sum[CH], g_sq[CH], g_r[CH];

__device__ __forceinline__ void mma16816h(float* d, const uint32_t* a, const uint32_t* b) {
    asm volatile(
        "mma.sync.aligned.m16n8k16.row.col.f32.f16.f16.f32 "
        "{%0,%1,%2,%3},{%4,%5,%6,%7},{%8,%9},{%0,%1,%2,%3};"
        : "+f"(d[0]), "+f"(d[1]), "+f"(d[2]), "+f"(d[3])
        : "r"(a[0]), "r"(a[1]), "r"(a[2]), "r"(a[3]), "r"(b[0]), "r"(b[1]));
}

// ---------------- prep kernels ----------------
__global__ void prep_w_kernel(const float* __restrict__ w1, const float* __restrict__ w2) {
    size_t i = (size_t)blockIdx.x*256 + threadIdx.x;
    if (i >= (size_t)2*WBLK*CC) return;
    size_t blk = i >> 14;
    int j = (int)(i & (CC-1));
    int ci = j >> 7, co = j & 127;
    float v = (blk < WBLK) ? w1[blk*CC + j] : w2[(blk - (size_t)WBLK)*CC + j];
    g_wq[blk*CC + (size_t)co*CH + ci] = __float2half_rn(v);
}

__global__ void prep_lin_kernel(const float* __restrict__ wlin) {
    int i = blockIdx.x*256 + threadIdx.x;
    if (i >= CC) return;
    int ci = i >> 7, co = i & 127;
    g_lwq[(size_t)co*CH + ci] = __float2half_rn(wlin[(size_t)ci*CH + co]);
}

__global__ void prep_x_kernel(const float* __restrict__ x) {
    size_t i = (size_t)blockIdx.x*256 + threadIdx.x;
    if (i >= (size_t)(NN+1)*CH) return;
    g_xq[i] = __float2half_rn(i < (size_t)NN*CH ? x[i] : 0.f);
}

// ---------------- fp16 sparse conv: register-staged double buffer ----------------
__global__ void __launch_bounds__(256, 1)
conv_f16_kernel(const __half* __restrict__ Aq, const __half* __restrict__ Wq,
                const int* __restrict__ nbr, int ntaps, const float* __restrict__ bias,
                float* __restrict__ outp, float* __restrict__ ps, float* __restrict__ pq)
{
    extern __shared__ char smem[];
    int* sidx = (int*)smem;

    __shared__ float sm_s[2][128], sm_q[2][128];

    const int tid = threadIdx.x, lane = tid & 31, warp = tid >> 5;
    const int wm = warp >> 2, wn = warp & 3;
    const int gr = lane >> 2;
    const int gc = (lane & 3) * 2;
    const int row0 = blockIdx.x * TILE_M;

    // per-thread load coordinates (fixed across taps)
    const int lr0 = tid >> 3;            // row for A/W chunk pairs: i = tid + p*256 -> r=i>>4
    (void)lr0;

    // prefetch neighbor indices for all taps
    for (int i = tid; i < ntaps*128; i += 256) {
        int rr = i & 127, k = i >> 7;
        int r = row0 + rr;
        sidx[i] = (r < NN) ? (nbr ? nbr[(size_t)k*NN + r] : r) : NN;
    }
    __syncthreads();

    uint4 ra[8], rw[8];

    // LDG for tap k into registers
    #define LDG_TAP(k) do {                                                     \
        const int* _sx = sidx + (k)*128;                                        \
        const __half* _wk = Wq + (size_t)(k)*CC;                                \
        _Pragma("unroll")                                                       \
        for (int _p = 0; _p < 8; ++_p) {                                        \
            int _c = tid + _p*256;                                              \
            int _r = _c >> 4, _g = _c & 15;                                     \
            ra[_p] = *(const uint4*)(Aq + (size_t)_sx[_r]*CH + _g*8);           \
            rw[_p] = *(const uint4*)(_wk + (size_t)_r*CH + _g*8);               \
        }                                                                       \
    } while (0)

    // STS registers into stage s
    #define STS_TAP(s) do {                                                     \
        char* _ab = smem + SIDX_BYTES + (s)*STAGE_BYTES;                        \
        char* _wb = _ab + 34816;                                                \
        _Pragma("unroll")                                                       \
        for (int _p = 0; _p < 8; ++_p) {                                        \
            int _c = tid + _p*256;                                              \
            int _r = _c >> 4, _g = _c & 15;                                     \
            *(uint4*)(_ab + _r*272 + _g*16) = ra[_p];                           \
            *(uint4*)(_wb + _r*272 + _g*16) = rw[_p];                           \
        }                                                                       \
    } while (0)

    // prologue
    LDG_TAP(0);
    STS_TAP(0);
    __syncthreads();

    float acc[4][4][4];
    #pragma unroll
    for (int a = 0; a < 4; a++)
        #pragma unroll
        for (int b = 0; b < 4; b++)
            #pragma unroll
            for (int c = 0; c < 4; c++) acc[a][b][c] = 0.f;

    #pragma unroll 1
    for (int k = 0; k < ntaps; ++k) {
        if (k + 1 < ntaps) LDG_TAP(k + 1);   // latency hidden behind MMAs

        const int s = k & 1;
        const __half* Ash = (const __half*)(smem + SIDX_BYTES + s*STAGE_BYTES);
        const __half* Wsh = Ash + 17408;

        #pragma unroll
        for (int kc = 0; kc < 8; ++kc) {
            const int kb = kc*16;
            uint32_t a_[4][4], b_[4][2];
            #pragma unroll
            for (int mi = 0; mi < 4; ++mi) {
                int rb = wm*64 + mi*16 + gr;
                int o0 = rb*136 + kb + gc;
                int o1 = (rb+8)*136 + kb + gc;
                a_[mi][0] = *(const uint32_t*)&Ash[o0];
                a_[mi][1] = *(const uint32_t*)&Ash[o1];
                a_[mi][2] = *(const uint32_t*)&Ash[o0 + 8];
                a_[mi][3] = *(const uint32_t*)&Ash[o1 + 8];
            }
            #pragma unroll
            for (int ni = 0; ni < 4; ++ni) {
                int nr = wn*32 + ni*8 + gr;
                int o = nr*136 + kb + gc;
                b_[ni][0] = *(const uint32_t*)&Wsh[o];
                b_[ni][1] = *(const uint32_t*)&Wsh[o + 8];
            }
            #pragma unroll
            for (int mi = 0; mi < 4; ++mi)
                #pragma unroll
                for (int ni = 0; ni < 4; ++ni)
                    mma16816h(acc[mi][ni], a_[mi], b_[ni]);
        }

        if (k + 1 < ntaps) STS_TAP(1 - s);   // write other stage (safe: last read 2 iters ago)
        __syncthreads();
    }

    // ---------------- epilogue: store + optional fused stats ----------------
    #pragma unroll
    for (int mi = 0; mi < 4; ++mi) {
        int r_ = row0 + wm*64 + mi*16 + gr;
        #pragma unroll
        for (int ni = 0; ni < 4; ++ni) {
            int col = wn*32 + ni*8 + gc;
            float v0 = acc[mi][ni][0], v1 = acc[mi][ni][1];
            float v2 = acc[mi][ni][2], v3 = acc[mi][ni][3];
            if (bias) { v0 += bias[col]; v1 += bias[col+1]; v2 += bias[col]; v3 += bias[col+1]; }
            if (r_ < NN)     *(float2*)&outp[(size_t)r_*CH + col]     = make_float2(v0, v1);
            if (r_ + 8 < NN) *(float2*)&outp[(size_t)(r_+8)*CH + col] = make_float2(v2, v3);
        }
    }

    if (ps) {
        #pragma unroll
        for (int ni = 0; ni < 4; ++ni) {
            #pragma unroll
            for (int u = 0; u < 2; ++u) {
                float s = 0.f, q = 0.f;
                #pragma unroll
                for (int mi = 0; mi < 4; ++mi) {
                    float p0 = acc[mi][ni][u], p1 = acc[mi][ni][u+2];
                    s += p0 + p1; q += p0*p0 + p1*p1;
                }
                #pragma unroll
                for (int off = 4; off < 32; off <<= 1) {
                    s += __shfl_xor_sync(0xFFFFFFFF, s, off);
                    q += __shfl_xor_sync(0xFFFFFFFF, q, off);
                }
                if (gr == 0) {
                    int col = wn*32 + ni*8 + gc + u;
                    sm_s[wm][col] = s; sm_q[wm][col] = q;
                }
            }
        }
        __syncthreads();
        if (tid < 128) {
            ps[(size_t)blockIdx.x*CH + tid] = sm_s[0][tid] + sm_s[1][tid];
            pq[(size_t)blockIdx.x*CH + tid] = sm_q[0][tid] + sm_q[1][tid];
        }
    }
    #undef LDG_TAP
    #undef STS_TAP
}

// ---------------- reduce partials -> g_sum, g_sq ----------------
__global__ void reduce_kernel(int cnt) {
    int c = threadIdx.x;
    float s0 = 0.f, q0 = 0.f, s1 = 0.f, q1 = 0.f;
    int b = 0;
    for (; b + 1 < cnt; b += 2) {
        s0 += g_ps[(size_t)b*CH + c];     q0 += g_pq[(size_t)b*CH + c];
        s1 += g_ps[(size_t)(b+1)*CH + c]; q1 += g_pq[(size_t)(b+1)*CH + c];
    }
    if (b < cnt) { s0 += g_ps[(size_t)b*CH + c]; q0 += g_pq[(size_t)b*CH + c]; }
    g_sum[c] = s0 + s1; g_sq[c] = q0 + q1;
}

// ---------------- BN + ReLU -> fp16 ----------------
__global__ void bn_relu_half_kernel(const float* __restrict__ h,
                                    const float* __restrict__ g, const float* __restrict__ b) {
    size_t i = (size_t)blockIdx.x*256 + threadIdx.x;
    if (i >= (size_t)(NN+1)*CH) return;
    int c = (int)(i & (CH-1));
    float val = 0.f;
    if (i < (size_t)NN*CH) {
        float m = g_sum[c] * (1.f/NN);
        float v = g_sq[c] * (1.f/NN) - m*m;
        float sc = g[c] * rsqrtf(v + 1e-5f);
        val = fmaxf((h[i] - m)*sc + b[c], 0.f);
    }
    g_hq[i] = __float2half_rn(val);
}

// ---------------- BN + accumulate into y ----------------
__global__ void bn_acc_kernel(const float* __restrict__ h,
                              const float* __restrict__ g, const float* __restrict__ b,
                              int first) {
    size_t i = (size_t)blockIdx.x*256 + threadIdx.x;
    if (i >= (size_t)NN*CH) return;
    int c = (int)(i & (CH-1));
    float m = g_sum[c] * (1.f/NN);
    float v = g_sq[c] * (1.f/NN) - m*m;
    float sc = g[c] * rsqrtf(v + 1e-5f);
    float bnv = (h[i] - m)*sc + b[c];
    g_ybuf[i] = first ? bnv : (g_ybuf[i] + bnv);
}

// ---------------- xout = relu(y + x) -> fp16 + column partial sums ----------------
__global__ void relu_add_kernel(const float* __restrict__ x) {
    int c = threadIdx.x;
    float s = 0.f;
    for (int r = blockIdx.x; r < NN; r += SB) {
        size_t i = (size_t)r*CH + c;
        float v = fmaxf(g_ybuf[i] + x[i], 0.f);
        g_hq[i] = __float2half_rn(v);
        s += v;
    }
    g_ps[(size_t)blockIdx.x*CH + c] = s;
    g_pq[(size_t)blockIdx.x*CH + c] = 0.f;
}

// ---------------- r = mean(xout) @ Wb + blin ----------------
__global__ void make_r_kernel(const float* __restrict__ wlin, const float* __restrict__ blin) {
    int co = threadIdx.x;
    float acc = blin[co];
    for (int ci = 0; ci < CH; ++ci)
        acc += (g_sum[ci] * (1.f/NN)) * wlin[(size_t)(CH + ci)*CH + co];
    g_r[co] = acc;
}

// ---------------- launch ----------------
extern "C" void kernel_launch(void* const* d_in, const int* in_sizes, int n_in,
                              void* d_out, int out_size) {
    const float* x    = (const float*)d_in[0];
    const float* w1   = (const float*)d_in[1];
    const float* w2   = (const float*)d_in[2];
    const float* g1   = (const float*)d_in[3];
    const float* b1   = (const float*)d_in[4];
    const float* g2   = (const float*)d_in[5];
    const float* b2   = (const float*)d_in[6];
    const float* wlin = (const float*)d_in[7];
    const float* blin = (const float*)d_in[8];
    const int*   nbr  = (const int*)d_in[9];
    float* outp = (float*)d_out;

    cudaFuncSetAttribute(conv_f16_kernel, cudaFuncAttributeMaxDynamicSharedMemorySize, SMEM_TOTAL);

    __half *xq, *hq, *wq, *lwq;
    float *h, *rptr, *ps, *pq;
    cudaGetSymbolAddress((void**)&xq,  g_xq);
    cudaGetSymbolAddress((void**)&hq,  g_hq);
    cudaGetSymbolAddress((void**)&wq,  g_wq);
    cudaGetSymbolAddress((void**)&lwq, g_lwq);
    cudaGetSymbolAddress((void**)&h,   g_hbuf);
    cudaGetSymbolAddress((void**)&rptr, g_r);
    cudaGetSymbolAddress((void**)&ps, g_ps);
    cudaGetSymbolAddress((void**)&pq, g_pq);

    size_t nq = (size_t)(NN+1)*CH;
    int qgrid = (int)((nq + 255)/256);

    prep_w_kernel<<<(int)((2ull*WBLK*CC + 255)/256), 256>>>(w1, w2);
    prep_lin_kernel<<<(CC + 255)/256, 256>>>(wlin);
    prep_x_kernel<<<qgrid, 256>>>(x);

    for (int d = 0; d < DD; ++d) {
        const int* nb = nbr + (size_t)d*KK*NN;
        conv_f16_kernel<<<NTIL, 256, SMEM_TOTAL>>>(xq,
            wq + (size_t)d*KK*CC, nb, KK, nullptr, h, ps, pq);
        reduce_kernel<<<1, CH>>>(NTIL);
        bn_relu_half_kernel<<<qgrid, 256>>>(h, g1 + d*CH, b1 + d*CH);
        conv_f16_kernel<<<NTIL, 256, SMEM_TOTAL>>>(hq,
            wq + (size_t)(WBLK + d*KK)*CC, nb, KK, nullptr, h, ps, pq);
        reduce_kernel<<<1, CH>>>(NTIL);
        bn_acc_kernel<<<(int)(((size_t)NN*CH + 255)/256), 256>>>(h, g2 + d*CH, b2 + d*CH, d == 0);
    }

    relu_add_kernel<<<SB, CH>>>(x);
    reduce_kernel<<<1, CH>>>(SB);
    make_r_kernel<<<1, CH>>>(wlin, blin);
    conv_f16_kernel<<<NTIL, 256, SMEM_TOTAL>>>(hq, lwq, nullptr, 1, rptr, outp, nullptr, nullptr);
}

// round 6
// speedup vs baseline: 7.7825x; 1.2517x over previous
#include <cuda_runtime.h>
#include <cuda_fp16.h>
#include <cstdint>

#define NN 200000
#define CH 128
#define KK 27
#define DD 3
#define CC (CH*CH)                  // 16384
#define WBLK (DD*KK)                // 81
#define SB 1024
#define TILE_M 128
#define NTIL ((NN + TILE_M - 1)/TILE_M)   // 1563

// dynamic smem: sidx[27*128] ints, then 2 stages of (A 34816B + W 34816B)
#define SIDX_BYTES (KK*128*4)             // 13824
#define STAGE_BYTES (2*128*272)           // 69632
#define SMEM_TOTAL (SIDX_BYTES + 2*STAGE_BYTES)   // 153088

// ---------------- device scratch ----------------
__device__ __align__(16) __half g_xq[(size_t)(NN+1)*CH];
__device__ __align__(16) __half g_hq[(size_t)(NN+1)*CH];
__device__ __align__(16) __half g_wq[(size_t)2*WBLK*CC];
__device__ __align__(16) __half g_lwq[CC];
__device__ __align__(16) float g_hbuf[(size_t)NN*CH];
__device__ __align__(16) float g_ybuf[(size_t)NN*CH];
__device__ float g_ps[1600*CH], g_pq[1600*CH];
__device__ float g_sum[CH], g_sq[CH], g_r[CH];

__device__ __forceinline__ uint32_t smem_u32(const void* p) {
    uint32_t a;
    asm("{ .reg .u64 t; cvta.to.shared.u64 t, %1; cvt.u32.u64 %0, t; }" : "=r"(a) : "l"(p));
    return a;
}

__device__ __forceinline__ void mma16816h(float* d, const uint32_t* a, const uint32_t* b) {
    asm volatile(
        "mma.sync.aligned.m16n8k16.row.col.f32.f16.f16.f32 "
        "{%0,%1,%2,%3},{%4,%5,%6,%7},{%8,%9},{%0,%1,%2,%3};"
        : "+f"(d[0]), "+f"(d[1]), "+f"(d[2]), "+f"(d[3])
        : "r"(a[0]), "r"(a[1]), "r"(a[2]), "r"(a[3]), "r"(b[0]), "r"(b[1]));
}

__device__ __forceinline__ void ldsm_x4(uint32_t* r, uint32_t addr) {
    asm volatile("ldmatrix.sync.aligned.m8n8.x4.shared.b16 {%0,%1,%2,%3}, [%4];"
        : "=r"(r[0]), "=r"(r[1]), "=r"(r[2]), "=r"(r[3]) : "r"(addr));
}

// ---------------- prep kernels ----------------
__global__ void prep_w_kernel(const float* __restrict__ w1, const float* __restrict__ w2) {
    size_t i = (size_t)blockIdx.x*256 + threadIdx.x;
    if (i >= (size_t)2*WBLK*CC) return;
    size_t blk = i >> 14;
    int j = (int)(i & (CC-1));
    int ci = j >> 7, co = j & 127;
    float v = (blk < WBLK) ? w1[blk*CC + j] : w2[(blk - (size_t)WBLK)*CC + j];
    g_wq[blk*CC + (size_t)co*CH + ci] = __float2half_rn(v);
}

__global__ void prep_lin_kernel(const float* __restrict__ wlin) {
    int i = blockIdx.x*256 + threadIdx.x;
    if (i >= CC) return;
    int ci = i >> 7, co = i & 127;
    g_lwq[(size_t)co*CH + ci] = __float2half_rn(wlin[(size_t)ci*CH + co]);
}

__global__ void prep_x_kernel(const float* __restrict__ x) {
    size_t i = (size_t)blockIdx.x*256 + threadIdx.x;   // group of 4 elements
    if (i >= (size_t)(NN+1)*CH/4) return;
    float4 v = (i < (size_t)NN*CH/4) ? ((const float4*)x)[i] : make_float4(0.f,0.f,0.f,0.f);
    __half2 h0 = __floats2half2_rn(v.x, v.y);
    __half2 h1 = __floats2half2_rn(v.z, v.w);
    ((uint2*)g_xq)[i] = make_uint2(*(uint32_t*)&h0, *(uint32_t*)&h1);
}

// ---------------- fp16 sparse conv: reg double-buffer + ldmatrix frags ----------------
__global__ void __launch_bounds__(256, 1)
conv_f16_kernel(const __half* __restrict__ Aq, const __half* __restrict__ Wq,
                const int* __restrict__ nbr, int ntaps, const float* __restrict__ bias,
                float* __restrict__ outp, float* __restrict__ ps, float* __restrict__ pq)
{
    extern __shared__ char smem[];
    int* sidx = (int*)smem;
    const uint32_t smemB = smem_u32(smem);

    __shared__ float sm_s[2][128], sm_q[2][128];

    const int tid = threadIdx.x, lane = tid & 31, warp = tid >> 5;
    const int wm = warp >> 2, wn = warp & 3;
    const int gr = lane >> 2;
    const int gc = (lane & 3) * 2;
    const int row0 = blockIdx.x * TILE_M;

    // ldmatrix lane address components (byte offsets within a tile)
    const int laneArow = ((lane >> 3) & 1)*8 + (lane & 7);
    const int acolb    = (lane >> 4) * 16;
    const int m8       = lane >> 3;
    const int laneBoff = ((m8 >> 1)*8 + (lane & 7))*272 + (m8 & 1)*16;

    // prefetch neighbor indices for all taps
    for (int i = tid; i < ntaps*128; i += 256) {
        int rr = i & 127, k = i >> 7;
        int r = row0 + rr;
        sidx[i] = (r < NN) ? (nbr ? nbr[(size_t)k*NN + r] : r) : NN;
    }
    __syncthreads();

    uint4 ra[8], rw[8];

    #define LDG_TAP(k) do {                                                     \
        const int* _sx = sidx + (k)*128;                                        \
        const __half* _wk = Wq + (size_t)(k)*CC;                                \
        _Pragma("unroll")                                                       \
        for (int _p = 0; _p < 8; ++_p) {                                        \
            int _c = tid + _p*256;                                              \
            int _r = _c >> 4, _g = _c & 15;                                     \
            ra[_p] = *(const uint4*)(Aq + (size_t)_sx[_r]*CH + _g*8);           \
            rw[_p] = *(const uint4*)(_wk + (size_t)_r*CH + _g*8);               \
        }                                                                       \
    } while (0)

    #define STS_TAP(s) do {                                                     \
        char* _ab = smem + SIDX_BYTES + (s)*STAGE_BYTES;                        \
        char* _wb = _ab + 34816;                                                \
        _Pragma("unroll")                                                       \
        for (int _p = 0; _p < 8; ++_p) {                                        \
            int _c = tid + _p*256;                                              \
            int _r = _c >> 4, _g = _c & 15;                                     \
            *(uint4*)(_ab + _r*272 + _g*16) = ra[_p];                           \
            *(uint4*)(_wb + _r*272 + _g*16) = rw[_p];                           \
        }                                                                       \
    } while (0)

    LDG_TAP(0);
    STS_TAP(0);
    __syncthreads();

    float acc[4][4][4];
    #pragma unroll
    for (int a = 0; a < 4; a++)
        #pragma unroll
        for (int b = 0; b < 4; b++)
            #pragma unroll
            for (int c = 0; c < 4; c++) acc[a][b][c] = 0.f;

    #pragma unroll 1
    for (int k = 0; k < ntaps; ++k) {
        if (k + 1 < ntaps) LDG_TAP(k + 1);

        const int s = k & 1;
        const uint32_t stage = smemB + SIDX_BYTES + s*STAGE_BYTES;
        const uint32_t aBase = stage + (uint32_t)(wm*64 + laneArow)*272 + acolb;
        const uint32_t bBase0 = stage + 34816 + (uint32_t)(wn*32 +  0)*272 + laneBoff;
        const uint32_t bBase1 = stage + 34816 + (uint32_t)(wn*32 + 16)*272 + laneBoff;

        #pragma unroll
        for (int kc = 0; kc < 8; ++kc) {
            uint32_t a_[4][4], b_[8];
            #pragma unroll
            for (int mi = 0; mi < 4; ++mi)
                ldsm_x4(a_[mi], aBase + mi*(16*272) + kc*32);
            ldsm_x4(b_,     bBase0 + kc*32);
            ldsm_x4(b_ + 4, bBase1 + kc*32);
            #pragma unroll
            for (int mi = 0; mi < 4; ++mi)
                #pragma unroll
                for (int ni = 0; ni < 4; ++ni)
                    mma16816h(acc[mi][ni], a_[mi], b_ + ni*2);
        }

        if (k + 1 < ntaps) STS_TAP(1 - s);
        __syncthreads();
    }

    // ---------------- epilogue: store + optional fused stats ----------------
    #pragma unroll
    for (int mi = 0; mi < 4; ++mi) {
        int r_ = row0 + wm*64 + mi*16 + gr;
        #pragma unroll
        for (int ni = 0; ni < 4; ++ni) {
            int col = wn*32 + ni*8 + gc;
            float v0 = acc[mi][ni][0], v1 = acc[mi][ni][1];
            float v2 = acc[mi][ni][2], v3 = acc[mi][ni][3];
            if (bias) { v0 += bias[col]; v1 += bias[col+1]; v2 += bias[col]; v3 += bias[col+1]; }
            if (r_ < NN)     *(float2*)&outp[(size_t)r_*CH + col]     = make_float2(v0, v1);
            if (r_ + 8 < NN) *(float2*)&outp[(size_t)(r_+8)*CH + col] = make_float2(v2, v3);
        }
    }

    if (ps) {
        #pragma unroll
        for (int ni = 0; ni < 4; ++ni) {
            #pragma unroll
            for (int u = 0; u < 2; ++u) {
                float s = 0.f, q = 0.f;
                #pragma unroll
                for (int mi = 0; mi < 4; ++mi) {
                    float p0 = acc[mi][ni][u], p1 = acc[mi][ni][u+2];
                    s += p0 + p1; q += p0*p0 + p1*p1;
                }
                #pragma unroll
                for (int off = 4; off < 32; off <<= 1) {
                    s += __shfl_xor_sync(0xFFFFFFFF, s, off);
                    q += __shfl_xor_sync(0xFFFFFFFF, q, off);
                }
                if (gr == 0) {
                    int col = wn*32 + ni*8 + gc + u;
                    sm_s[wm][col] = s; sm_q[wm][col] = q;
                }
            }
        }
        __syncthreads();
        if (tid < 128) {
            ps[(size_t)blockIdx.x*CH + tid] = sm_s[0][tid] + sm_s[1][tid];
            pq[(size_t)blockIdx.x*CH + tid] = sm_q[0][tid] + sm_q[1][tid];
        }
    }
    #undef LDG_TAP
    #undef STS_TAP
}

// ---------------- parallel deterministic reduce: grid=CH blocks ----------------
__global__ void reduce2_kernel(int cnt) {
    int c = blockIdx.x;
    int t = threadIdx.x;   // 256
    float s = 0.f, q = 0.f;
    for (int b = t; b < cnt; b += 256) {
        s += g_ps[(size_t)b*CH + c];
        q += g_pq[(size_t)b*CH + c];
    }
    __shared__ float ss[256], qq[256];
    ss[t] = s; qq[t] = q; __syncthreads();
    for (int st = 128; st > 0; st >>= 1) {
        if (t < st) { ss[t] += ss[t+st]; qq[t] += qq[t+st]; }
        __syncthreads();
    }
    if (!t) { g_sum[c] = ss[0]; g_sq[c] = qq[0]; }
}

// ---------------- BN + ReLU -> fp16 (vectorized x4) ----------------
__global__ void bn_relu_half_kernel(const float* __restrict__ h,
                                    const float* __restrict__ g, const float* __restrict__ b) {
    size_t i = (size_t)blockIdx.x*256 + threadIdx.x;   // group of 4
    if (i >= (size_t)(NN+1)*CH/4) return;
    int c0 = (int)((i*4) & (CH-1));
    float4 hv = (i < (size_t)NN*CH/4) ? ((const float4*)h)[i] : make_float4(0.f,0.f,0.f,0.f);
    float o[4]; float* hp = &hv.x;
    #pragma unroll
    for (int j = 0; j < 4; ++j) {
        int c = c0 + j;
        float m = g_sum[c] * (1.f/NN);
        float v = g_sq[c] * (1.f/NN) - m*m;
        float sc = g[c] * rsqrtf(v + 1e-5f);
        o[j] = (i < (size_t)NN*CH/4) ? fmaxf((hp[j] - m)*sc + b[c], 0.f) : 0.f;
    }
    __half2 h0 = __floats2half2_rn(o[0], o[1]);
    __half2 h1 = __floats2half2_rn(o[2], o[3]);
    ((uint2*)g_hq)[i] = make_uint2(*(uint32_t*)&h0, *(uint32_t*)&h1);
}

// ---------------- BN + accumulate into y (vectorized x4, d=0/1) ----------------
__global__ void bn_acc_kernel(const float* __restrict__ h,
                              const float* __restrict__ g, const float* __restrict__ b,
                              int first) {
    size_t i = (size_t)blockIdx.x*256 + threadIdx.x;   // group of 4
    if (i >= (size_t)NN*CH/4) return;
    int c0 = (int)((i*4) & (CH-1));
    float4 hv = ((const float4*)h)[i];
    float4 yv = first ? make_float4(0.f,0.f,0.f,0.f) : ((const float4*)g_ybuf)[i];
    float* hp = &hv.x; float* yp = &yv.x;
    #pragma unroll
    for (int j = 0; j < 4; ++j) {
        int c = c0 + j;
        float m = g_sum[c] * (1.f/NN);
        float v = g_sq[c] * (1.f/NN) - m*m;
        float sc = g[c] * rsqrtf(v + 1e-5f);
        yp[j] += (hp[j] - m)*sc + b[c];
    }
    ((float4*)g_ybuf)[i] = yv;
}

// ---------------- fused: BN(d=2) + y + x, ReLU -> fp16 + column sums ----------------
__global__ void bn_acc_relu_kernel(const float* __restrict__ h,
                                   const float* __restrict__ g, const float* __restrict__ b,
                                   const float* __restrict__ x) {
    int c = threadIdx.x;
    float m = g_sum[c] * (1.f/NN);
    float var = g_sq[c] * (1.f/NN) - m*m;
    float sc = g[c] * rsqrtf(var + 1e-5f);
    float bb = b[c];
    float s = 0.f;
    for (int r = blockIdx.x; r < NN; r += SB) {
        size_t i = (size_t)r*CH + c;
        float v = fmaxf(g_ybuf[i] + (h[i] - m)*sc + bb + x[i], 0.f);
        g_hq[i] = __float2half_rn(v);
        s += v;
    }
    g_ps[(size_t)blockIdx.x*CH + c] = s;
    g_pq[(size_t)blockIdx.x*CH + c] = 0.f;
}

// ---------------- r = mean(xout) @ Wb + blin ----------------
__global__ void make_r_kernel(const float* __restrict__ wlin, const float* __restrict__ blin) {
    int co = threadIdx.x;
    float acc = blin[co];
    for (int ci = 0; ci < CH; ++ci)
        acc += (g_sum[ci] * (1.f/NN)) * wlin[(size_t)(CH + ci)*CH + co];
    g_r[co] = acc;
}

// ---------------- launch ----------------
extern "C" void kernel_launch(void* const* d_in, const int* in_sizes, int n_in,
                              void* d_out, int out_size) {
    const float* x    = (const float*)d_in[0];
    const float* w1   = (const float*)d_in[1];
    const float* w2   = (const float*)d_in[2];
    const float* g1   = (const float*)d_in[3];
    const float* b1   = (const float*)d_in[4];
    const float* g2   = (const float*)d_in[5];
    const float* b2   = (const float*)d_in[6];
    const float* wlin = (const float*)d_in[7];
    const float* blin = (const float*)d_in[8];
    const int*   nbr  = (const int*)d_in[9];
    float* outp = (float*)d_out;

    cudaFuncSetAttribute(conv_f16_kernel, cudaFuncAttributeMaxDynamicSharedMemorySize, SMEM_TOTAL);

    __half *xq, *hq, *wq, *lwq;
    float *h, *rptr, *ps, *pq;
    cudaGetSymbolAddress((void**)&xq,  g_xq);
    cudaGetSymbolAddress((void**)&hq,  g_hq);
    cudaGetSymbolAddress((void**)&wq,  g_wq);
    cudaGetSymbolAddress((void**)&lwq, g_lwq);
    cudaGetSymbolAddress((void**)&h,   g_hbuf);
    cudaGetSymbolAddress((void**)&rptr, g_r);
    cudaGetSymbolAddress((void**)&ps, g_ps);
    cudaGetSymbolAddress((void**)&pq, g_pq);

    size_t nq4 = (size_t)(NN+1)*CH/4;
    int qgrid4 = (int)((nq4 + 255)/256);
    int agrid4 = (int)(((size_t)NN*CH/4 + 255)/256);

    prep_w_kernel<<<(int)((2ull*WBLK*CC + 255)/256), 256>>>(w1, w2);
    prep_lin_kernel<<<(CC + 255)/256, 256>>>(wlin);
    prep_x_kernel<<<qgrid4, 256>>>(x);

    for (int d = 0; d < DD; ++d) {
        const int* nb = nbr + (size_t)d*KK*NN;
        conv_f16_kernel<<<NTIL, 256, SMEM_TOTAL>>>(xq,
            wq + (size_t)d*KK*CC, nb, KK, nullptr, h, ps, pq);
        reduce2_kernel<<<CH, 256>>>(NTIL);
        bn_relu_half_kernel<<<qgrid4, 256>>>(h, g1 + d*CH, b1 + d*CH);
        conv_f16_kernel<<<NTIL, 256, SMEM_TOTAL>>>(hq,
            wq + (size_t)(WBLK + d*KK)*CC, nb, KK, nullptr, h, ps, pq);
        reduce2_kernel<<<CH, 256>>>(NTIL);
        if (d < DD-1)
            bn_acc_kernel<<<agrid4, 256>>>(h, g2 + d*CH, b2 + d*CH, d == 0);
        else
            bn_acc_relu_kernel<<<SB, CH>>>(h, g2 + d*CH, b2 + d*CH, x);
    }

    reduce2_kernel<<<CH, 256>>>(SB);
    make_r_kernel<<<1, CH>>>(wlin, blin);
    conv_f16_kernel<<<NTIL, 256, SMEM_TOTAL>>>(hq, lwq, nullptr, 1, rptr, outp, nullptr, nullptr);
}